// round 8
// baseline (speedup 1.0000x reference)
#include <cuda_runtime.h>
#include <cstdint>

#define BATCH 8
#define SEQ   2048
#define EMB   1024
#define HEAD  64
#define NTOK  (BATCH*SEQ)   // 16384
#define LOG2E 1.4426950408889634f
#define QSCALE (0.03125f * LOG2E)   // C^-0.5 * log2(e)

// ---------------------------------------------------------------------------
// PTX helpers (family-portable only)
// ---------------------------------------------------------------------------
__device__ __forceinline__ float tf32r(float x) {
    float y; asm("cvt.rna.tf32.f32 %0, %1;" : "=f"(y) : "f"(x)); return y;
}
__device__ __forceinline__ void mma_tf32(float* d, const uint32_t* a, const uint32_t* b) {
    asm volatile(
        "mma.sync.aligned.m16n8k8.row.col.f32.tf32.tf32.f32 "
        "{%0,%1,%2,%3}, {%4,%5,%6,%7}, {%8,%9}, {%0,%1,%2,%3};"
        : "+f"(d[0]), "+f"(d[1]), "+f"(d[2]), "+f"(d[3])
        : "r"(a[0]), "r"(a[1]), "r"(a[2]), "r"(a[3]), "r"(b[0]), "r"(b[1]));
}

// ---------------------------------------------------------------------------
// device scratch (Q pre-scaled; Q,K,V tf32-rounded at production)
// ---------------------------------------------------------------------------
__device__ float g_Q[NTOK*HEAD];
__device__ float g_K[NTOK*HEAD];
__device__ float g_V[NTOK*HEAD];

// ---------------------------------------------------------------------------
// Kernel 1: QKV projection, mma.sync tf32.  M-tile 64 -> grid 256 -> 2 CTA/SM.
// 256 threads = 8 warps: mw = wid>>1 (16 m-rows), nw = wid&1 (32 n-cols).
// smem (static): XsT[32][68] | Ws[3][32][68] = 34816 B
// ---------------------------------------------------------------------------
__global__ __launch_bounds__(256, 2) void qkv_mma(
    const float* __restrict__ X,
    const float* __restrict__ Wq,
    const float* __restrict__ Wk,
    const float* __restrict__ Wv)
{
    __shared__ float XsT[32][68];     // [k][m] transposed
    __shared__ float Ws[3][32][68];   // [w][k][n]

    const int tid  = threadIdx.x;
    const int wid  = tid >> 5;
    const int lane = tid & 31;
    const int mw   = wid >> 1;        // 0..3
    const int nw   = wid & 1;         // 0..1
    const int m0   = blockIdx.x * 64;
    const int r = lane >> 2;
    const int c = lane & 3;

    const float* Wsrc[3] = { Wq, Wk, Wv };

    float acc[3][4][4];
    #pragma unroll
    for (int w = 0; w < 3; w++)
        #pragma unroll
        for (int nf = 0; nf < 4; nf++)
            #pragma unroll
            for (int e = 0; e < 4; e++) acc[w][nf][e] = 0.f;

    for (int kt = 0; kt < 32; kt++) {
        __syncthreads();
        // X tile 64x32 -> transposed (512 f4, 2/thread), tf32-rounded
        #pragma unroll
        for (int it = 0; it < 2; it++) {
            int f = tid + it * 256, cc = f & 7, rr = f >> 3;
            float4 v = *(const float4*)&X[(size_t)(m0 + rr) * EMB + kt*32 + 4*cc];
            XsT[4*cc + 0][rr] = tf32r(v.x);
            XsT[4*cc + 1][rr] = tf32r(v.y);
            XsT[4*cc + 2][rr] = tf32r(v.z);
            XsT[4*cc + 3][rr] = tf32r(v.w);
        }
        // W tiles 3 x 32x64 (1536 f4, 6/thread)
        #pragma unroll
        for (int it = 0; it < 6; it++) {
            int f = tid + it * 256, w = f >> 9, rem = f & 511;
            int cc = rem & 15, rr = rem >> 4;
            float4 v = *(const float4*)&Wsrc[w][(size_t)(kt*32 + rr) * HEAD + 4*cc];
            v.x = tf32r(v.x); v.y = tf32r(v.y); v.z = tf32r(v.z); v.w = tf32r(v.w);
            *(float4*)&Ws[w][rr][4*cc] = v;
        }
        __syncthreads();

        #pragma unroll
        for (int ks = 0; ks < 4; ks++) {
            const int k = ks * 8;
            const int m = mw * 16;
            uint32_t a[4];
            a[0] = __float_as_uint(XsT[k + c    ][m + r    ]);
            a[1] = __float_as_uint(XsT[k + c    ][m + r + 8]);
            a[2] = __float_as_uint(XsT[k + c + 4][m + r    ]);
            a[3] = __float_as_uint(XsT[k + c + 4][m + r + 8]);
            #pragma unroll
            for (int w = 0; w < 3; w++) {
                #pragma unroll
                for (int nf = 0; nf < 4; nf++) {
                    const int n = nw*32 + nf*8;
                    uint32_t b[2];
                    b[0] = __float_as_uint(Ws[w][k + c    ][n + r]);
                    b[1] = __float_as_uint(Ws[w][k + c + 4][n + r]);
                    mma_tf32(acc[w][nf], a, b);
                }
            }
        }
    }

    // epilogue: Q pre-scaled; all tf32-rounded for the attention kernel
    #pragma unroll
    for (int w = 0; w < 3; w++) {
        float* Out = (w == 0) ? g_Q : (w == 1) ? g_K : g_V;
        const float sc = (w == 0) ? QSCALE : 1.f;
        const int mrow = m0 + mw*16 + r;
        #pragma unroll
        for (int nf = 0; nf < 4; nf++) {
            const int n = nw*32 + nf*8 + 2*c;
            *(float2*)&Out[(size_t)mrow * HEAD + n] =
                make_float2(tf32r(acc[w][nf][0] * sc), tf32r(acc[w][nf][1] * sc));
            *(float2*)&Out[(size_t)(mrow + 8) * HEAD + n] =
                make_float2(tf32r(acc[w][nf][2] * sc), tf32r(acc[w][nf][3] * sc));
        }
    }
}

// ---------------------------------------------------------------------------
// Kernel 2: flash attention, mma.sync tf32.
// q-tile 32, kv-tile 128, pairs {p, 63-p} -> exactly 17 tiles per CTA.
// grid (32, 8) = 256 CTAs, 256 threads, 2 CTAs/SM.
// warps: mw = wid>>2 (16 q-rows of 32), nw = wid&3 (32 keys / 16 head-cols).
// smem (floats): Qs 32x68 | Ks 128x68 (alias Ps 32x132) | Vs 128x68 | red 256
// = 2176 + 8704 + 8704 + 256 = 19840 floats = 79360 B
// ---------------------------------------------------------------------------
#define ATTN_SMEM_BYTES (19840 * 4)

__global__ __launch_bounds__(256, 2) void attn_mma(float* __restrict__ out)
{
    extern __shared__ float sm[];
    float* Qs = sm;                  // 2176, pitch 68
    float* Ks = sm + 2176;           // 8704, pitch 68
    float* Ps = Ks;                  // 4224, pitch 132 (alias)
    float* Vs = sm + 10880;          // 8704, pitch 68
    float* redmax = sm + 19584;      // [4][32]
    float* redsum = redmax + 128;    // [4][32]

    const int tid  = threadIdx.x;
    const int wid  = tid >> 5;
    const int lane = tid & 31;
    const int mw   = wid >> 2;        // 0..1
    const int nw   = wid & 3;         // 0..3
    const int r    = lane >> 2;
    const int c    = lane & 3;
    const int b    = blockIdx.y;

    const float* Qg = g_Q + (size_t)b * SEQ * HEAD;
    const float* Kg = g_K + (size_t)b * SEQ * HEAD;
    const float* Vg = g_V + (size_t)b * SEQ * HEAD;

    const int rowbase = mw*16 + r;    // 0..23 (r<8)

    #pragma unroll 1
    for (int half = 0; half < 2; half++) {
        const int qb = half ? (63 - (int)blockIdx.x) : (int)blockIdx.x;
        const int q0 = qb * 32;
        const int ntiles = q0 / 128 + 1;

        // stage Q (pre-scaled + tf32 at producer): 512 f4, 2/thread
        #pragma unroll
        for (int it = 0; it < 2; it++) {
            int f = tid + it * 256, cc = f & 15, rr = f >> 4;
            *(float4*)&Qs[rr*68 + 4*cc] =
                *(const float4*)&Qg[(size_t)(q0 + rr) * HEAD + 4*cc];
        }

        float m_st[2] = { -1e30f, -1e30f };
        float l_st[2] = { 0.f, 0.f };
        float o[2][4];
        #pragma unroll
        for (int nf = 0; nf < 2; nf++)
            #pragma unroll
            for (int e = 0; e < 4; e++) o[nf][e] = 0.f;

        for (int kt = 0; kt < ntiles; kt++) {
            const int k0 = kt * 128;
            __syncthreads();   // PV(kt-1) done with Ps(=Ks)/Vs; Q visible

            // stage K,V tiles 128x64 (2048 f4 each, 8+8 per thread)
            #pragma unroll
            for (int it = 0; it < 8; it++) {
                int f = tid + it * 256, cc = f & 15, rr = f >> 4;
                *(float4*)&Ks[rr*68 + 4*cc] =
                    *(const float4*)&Kg[(size_t)(k0 + rr) * HEAD + 4*cc];
                *(float4*)&Vs[rr*68 + 4*cc] =
                    *(const float4*)&Vg[(size_t)(k0 + rr) * HEAD + 4*cc];
            }
            __syncthreads();

            // ----- S = Q K^T : warp tile 16q x 32keys -----
            float s[4][4];
            #pragma unroll
            for (int nf = 0; nf < 4; nf++)
                #pragma unroll
                for (int e = 0; e < 4; e++) s[nf][e] = 0.f;

            #pragma unroll
            for (int ks = 0; ks < 8; ks++) {
                const int k = ks * 8;
                uint32_t a[4];
                a[0] = __float_as_uint(Qs[(mw*16 + r    )*68 + k + c    ]);
                a[1] = __float_as_uint(Qs[(mw*16 + r + 8)*68 + k + c    ]);
                a[2] = __float_as_uint(Qs[(mw*16 + r    )*68 + k + c + 4]);
                a[3] = __float_as_uint(Qs[(mw*16 + r + 8)*68 + k + c + 4]);
                #pragma unroll
                for (int nf = 0; nf < 4; nf++) {
                    const int n = nw*32 + nf*8;
                    uint32_t bb[2];
                    bb[0] = __float_as_uint(Ks[(n + r)*68 + k + c    ]);
                    bb[1] = __float_as_uint(Ks[(n + r)*68 + k + c + 4]);
                    mma_tf32(s[nf], a, bb);
                }
            }

            // ----- causal mask -----
            const int row0 = q0 + mw*16 + r;
            const int row1 = row0 + 8;
            if (k0 + 127 > q0) {
                #pragma unroll
                for (int nf = 0; nf < 4; nf++) {
                    const int col = k0 + nw*32 + nf*8 + 2*c;
                    if (col     > row0) s[nf][0] = -1e30f;
                    if (col + 1 > row0) s[nf][1] = -1e30f;
                    if (col     > row1) s[nf][2] = -1e30f;
                    if (col + 1 > row1) s[nf][3] = -1e30f;
                }
            }

            // ----- row max: intra-warp over c, 4-way cross-warp via smem ---
            float pm0 = s[0][0], pm1 = s[0][2];
            #pragma unroll
            for (int nf = 0; nf < 4; nf++) {
                pm0 = fmaxf(pm0, fmaxf(s[nf][0], s[nf][1]));
                pm1 = fmaxf(pm1, fmaxf(s[nf][2], s[nf][3]));
            }
            #pragma unroll
            for (int off = 1; off <= 2; off <<= 1) {
                pm0 = fmaxf(pm0, __shfl_xor_sync(0xffffffffu, pm0, off));
                pm1 = fmaxf(pm1, __shfl_xor_sync(0xffffffffu, pm1, off));
            }
            if (c == 0) {
                redmax[nw*32 + rowbase    ] = pm0;
                redmax[nw*32 + rowbase + 8] = pm1;
            }
            __syncthreads();   // (A) also: QK reads of Ks complete

            float mn0 = m_st[0], mn1 = m_st[1];
            #pragma unroll
            for (int g = 0; g < 4; g++) {
                mn0 = fmaxf(mn0, redmax[g*32 + rowbase    ]);
                mn1 = fmaxf(mn1, redmax[g*32 + rowbase + 8]);
            }
            float corr0 = exp2f(m_st[0] - mn0);
            float corr1 = exp2f(m_st[1] - mn1);
            m_st[0] = mn0; m_st[1] = mn1;

            float rs0 = 0.f, rs1 = 0.f;
            #pragma unroll
            for (int nf = 0; nf < 4; nf++) {
                float p0 = exp2f(s[nf][0] - mn0);
                float p1 = exp2f(s[nf][1] - mn0);
                float p2 = exp2f(s[nf][2] - mn1);
                float p3 = exp2f(s[nf][3] - mn1);
                rs0 += p0 + p1;
                rs1 += p2 + p3;
                const int col = nw*32 + nf*8 + 2*c;
                *(float2*)&Ps[(rowbase    )*132 + col] =
                    make_float2(tf32r(p0), tf32r(p1));
                *(float2*)&Ps[(rowbase + 8)*132 + col] =
                    make_float2(tf32r(p2), tf32r(p3));
            }
            #pragma unroll
            for (int off = 1; off <= 2; off <<= 1) {
                rs0 += __shfl_xor_sync(0xffffffffu, rs0, off);
                rs1 += __shfl_xor_sync(0xffffffffu, rs1, off);
            }
            if (c == 0) {
                redsum[nw*32 + rowbase    ] = rs0;
                redsum[nw*32 + rowbase + 8] = rs1;
            }
            __syncthreads();   // (B) P + redsum visible

            float sum0 = 0.f, sum1 = 0.f;
            #pragma unroll
            for (int g = 0; g < 4; g++) {
                sum0 += redsum[g*32 + rowbase    ];
                sum1 += redsum[g*32 + rowbase + 8];
            }
            l_st[0] = l_st[0] * corr0 + sum0;
            l_st[1] = l_st[1] * corr1 + sum1;

            #pragma unroll
            for (int nf = 0; nf < 2; nf++) {
                o[nf][0] *= corr0; o[nf][1] *= corr0;
                o[nf][2] *= corr1; o[nf][3] *= corr1;
            }

            // ----- O += P V : warp tile 16q x 16head -----
            #pragma unroll
            for (int ks = 0; ks < 16; ks++) {
                const int k = ks * 8;
                uint32_t a[4];
                a[0] = __float_as_uint(Ps[(mw*16 + r    )*132 + k + c    ]);
                a[1] = __float_as_uint(Ps[(mw*16 + r + 8)*132 + k + c    ]);
                a[2] = __float_as_uint(Ps[(mw*16 + r    )*132 + k + c + 4]);
                a[3] = __float_as_uint(Ps[(mw*16 + r + 8)*132 + k + c + 4]);
                #pragma unroll
                for (int nf = 0; nf < 2; nf++) {
                    const int n = nw*16 + nf*8;
                    uint32_t bb[2];
                    bb[0] = __float_as_uint(Vs[(k + c    )*68 + n + r]);
                    bb[1] = __float_as_uint(Vs[(k + c + 4)*68 + n + r]);
                    mma_tf32(o[nf], a, bb);
                }
            }
        }

        // epilogue: normalize, store
        const int row0 = q0 + mw*16 + r;
        const float inv0 = 1.f / l_st[0];
        const float inv1 = 1.f / l_st[1];
        #pragma unroll
        for (int nf = 0; nf < 2; nf++) {
            const int n = nw*16 + nf*8 + 2*c;
            *(float2*)&out[((size_t)b * SEQ + row0) * HEAD + n] =
                make_float2(o[nf][0] * inv0, o[nf][1] * inv0);
            *(float2*)&out[((size_t)b * SEQ + row0 + 8) * HEAD + n] =
                make_float2(o[nf][2] * inv1, o[nf][3] * inv1);
        }
        __syncthreads();   // all smem reads done before next half restages
    }
}

// ---------------------------------------------------------------------------
extern "C" void kernel_launch(void* const* d_in, const int* in_sizes, int n_in,
                              void* d_out, int out_size)
{
    const float* X  = (const float*)d_in[0];
    const float* Wq = (const float*)d_in[1];
    const float* Wk = (const float*)d_in[2];
    const float* Wv = (const float*)d_in[3];
    float* out = (float*)d_out;

    cudaFuncSetAttribute(attn_mma,
                         cudaFuncAttributeMaxDynamicSharedMemorySize, ATTN_SMEM_BYTES);

    qkv_mma<<<NTOK / 64, 256>>>(X, Wq, Wk, Wv);

    dim3 g2(32, BATCH);
    attn_mma<<<g2, 256, ATTN_SMEM_BYTES>>>(out);
}

// round 9
// speedup vs baseline: 1.4402x; 1.4402x over previous
#include <cuda_runtime.h>
#include <cstdint>

#define BATCH 8
#define SEQ   2048
#define EMB   1024
#define HEAD  64
#define NTOK  (BATCH*SEQ)   // 16384
#define LOG2E 1.4426950408889634f
#define QSCALE (0.03125f * LOG2E)   // C^-0.5 * log2(e)

// ---------------------------------------------------------------------------
// PTX helpers (family-portable only)
// ---------------------------------------------------------------------------
__device__ __forceinline__ float tf32r(float x) {
    float y; asm("cvt.rna.tf32.f32 %0, %1;" : "=f"(y) : "f"(x)); return y;
}
__device__ __forceinline__ void mma_tf32(float* d, const uint32_t* a, const uint32_t* b) {
    asm volatile(
        "mma.sync.aligned.m16n8k8.row.col.f32.tf32.tf32.f32 "
        "{%0,%1,%2,%3}, {%4,%5,%6,%7}, {%8,%9}, {%0,%1,%2,%3};"
        : "+f"(d[0]), "+f"(d[1]), "+f"(d[2]), "+f"(d[3])
        : "r"(a[0]), "r"(a[1]), "r"(a[2]), "r"(a[3]), "r"(b[0]), "r"(b[1]));
}
__device__ __forceinline__ uint32_t s32(const void* p) {
    return (uint32_t)__cvta_generic_to_shared(p);
}
#define CP_ASYNC16(dst, src) \
    asm volatile("cp.async.cg.shared.global [%0], [%1], 16;" :: "r"(dst), "l"(src))
#define CP_COMMIT() asm volatile("cp.async.commit_group;" ::: "memory")
#define CP_WAIT0()  asm volatile("cp.async.wait_group 0;" ::: "memory")

// ---------------------------------------------------------------------------
// device scratch (Q pre-scaled; Q,K,V tf32-rounded at production)
// ---------------------------------------------------------------------------
__device__ float g_Q[NTOK*HEAD];
__device__ float g_K[NTOK*HEAD];
__device__ float g_V[NTOK*HEAD];

// ---------------------------------------------------------------------------
// Kernel 1: QKV projection, mma.sync tf32.
// M-tile 128, K-tile 64, grid 128, 256 threads = 8 warps (4m x 2n).
// X staged NATURAL row-major (A-frags read conflict-free, no transpose).
// smem (dynamic): Xs[128][68] | Ws[3][64][68] = 21760 floats = 87040 B
// ---------------------------------------------------------------------------
#define QKV_SMEM_BYTES (21760 * 4)

__global__ __launch_bounds__(256, 1) void qkv_mma(
    const float* __restrict__ X,
    const float* __restrict__ Wq,
    const float* __restrict__ Wk,
    const float* __restrict__ Wv)
{
    extern __shared__ float qsm[];
    float* Xs = qsm;            // [m][k], pitch 68
    float* Ws = qsm + 8704;     // [w][k][n], pitch 68, 64 k-rows per w

    const int tid  = threadIdx.x;
    const int wid  = tid >> 5;
    const int lane = tid & 31;
    const int mw   = wid >> 1;        // 0..3 (32 m-rows)
    const int nw   = wid & 1;         // 0..1 (32 n-cols)
    const int m0   = blockIdx.x * 128;
    const int r = lane >> 2;
    const int c = lane & 3;

    const float* Wsrc[3] = { Wq, Wk, Wv };

    float acc[3][2][4][4];
    #pragma unroll
    for (int w = 0; w < 3; w++)
        #pragma unroll
        for (int mf = 0; mf < 2; mf++)
            #pragma unroll
            for (int nf = 0; nf < 4; nf++)
                #pragma unroll
                for (int e = 0; e < 4; e++) acc[w][mf][nf][e] = 0.f;

    for (int kt = 0; kt < 16; kt++) {          // 16 K-tiles of 64
        __syncthreads();
        // X tile 128x64 natural (2048 f4, 8/thread), tf32-rounded
        #pragma unroll
        for (int it = 0; it < 8; it++) {
            int f = tid + it * 256, cc = f & 15, rr = f >> 4;
            float4 v = *(const float4*)&X[(size_t)(m0 + rr) * EMB + kt*64 + 4*cc];
            v.x = tf32r(v.x); v.y = tf32r(v.y); v.z = tf32r(v.z); v.w = tf32r(v.w);
            *(float4*)&Xs[rr*68 + 4*cc] = v;
        }
        // W tiles 3 x 64x64 (3072 f4, 12/thread)
        #pragma unroll
        for (int it = 0; it < 12; it++) {
            int f = tid + it * 256, w = f >> 10, rem = f & 1023;
            int cc = rem & 15, rr = rem >> 4;
            float4 v = *(const float4*)&Wsrc[w][(size_t)(kt*64 + rr) * HEAD + 4*cc];
            v.x = tf32r(v.x); v.y = tf32r(v.y); v.z = tf32r(v.z); v.w = tf32r(v.w);
            *(float4*)&Ws[w*4352 + rr*68 + 4*cc] = v;
        }
        __syncthreads();

        #pragma unroll
        for (int ks = 0; ks < 8; ks++) {
            const int k = ks * 8;
            uint32_t a[2][4];
            #pragma unroll
            for (int mf = 0; mf < 2; mf++) {
                const int m = mw*32 + mf*16;
                a[mf][0] = __float_as_uint(Xs[(m + r    )*68 + k + c    ]);
                a[mf][1] = __float_as_uint(Xs[(m + r + 8)*68 + k + c    ]);
                a[mf][2] = __float_as_uint(Xs[(m + r    )*68 + k + c + 4]);
                a[mf][3] = __float_as_uint(Xs[(m + r + 8)*68 + k + c + 4]);
            }
            #pragma unroll
            for (int w = 0; w < 3; w++) {
                uint32_t b[4][2];
                #pragma unroll
                for (int nf = 0; nf < 4; nf++) {
                    const int n = nw*32 + nf*8;
                    b[nf][0] = __float_as_uint(Ws[w*4352 + (k + c    )*68 + n + r]);
                    b[nf][1] = __float_as_uint(Ws[w*4352 + (k + c + 4)*68 + n + r]);
                }
                #pragma unroll
                for (int mf = 0; mf < 2; mf++)
                    #pragma unroll
                    for (int nf = 0; nf < 4; nf++)
                        mma_tf32(acc[w][mf][nf], a[mf], b[nf]);
            }
        }
    }

    // epilogue: Q pre-scaled; all tf32-rounded for the attention kernel
    #pragma unroll
    for (int w = 0; w < 3; w++) {
        float* Out = (w == 0) ? g_Q : (w == 1) ? g_K : g_V;
        const float sc = (w == 0) ? QSCALE : 1.f;
        #pragma unroll
        for (int mf = 0; mf < 2; mf++) {
            const int mrow = m0 + mw*32 + mf*16 + r;
            #pragma unroll
            for (int nf = 0; nf < 4; nf++) {
                const int n = nw*32 + nf*8 + 2*c;
                *(float2*)&Out[(size_t)mrow * HEAD + n] =
                    make_float2(tf32r(acc[w][mf][nf][0] * sc),
                                tf32r(acc[w][mf][nf][1] * sc));
                *(float2*)&Out[(size_t)(mrow + 8) * HEAD + n] =
                    make_float2(tf32r(acc[w][mf][nf][2] * sc),
                                tf32r(acc[w][mf][nf][3] * sc));
            }
        }
    }
}

// ---------------------------------------------------------------------------
// Kernel 2: flash attention, mma.sync tf32, kv-tile 256.
// q-tile 64, pairs {p, 31-p} -> exactly 9 kv-tiles of 256 per CTA.
// grid (16, 8) = 128 CTAs, 256 threads = 8 warps (4m x 2n).
// smem (floats): Qs 64x68 | Ks 256x68 (alias Ps 64x260) | Vs 256x68 | red 256
// = 4352 + 17408 + 17408 + 256 = 39424 floats = 157696 B
// ---------------------------------------------------------------------------
#define ATTN_SMEM_BYTES (39424 * 4)

__global__ __launch_bounds__(256, 1) void attn_mma(float* __restrict__ out)
{
    extern __shared__ float sm[];
    float* Qs = sm;                  // pitch 68
    float* Ks = sm + 4352;           // pitch 68, 256 rows
    float* Ps = Ks;                  // pitch 260, 64 rows (alias, 16640 <= 17408)
    float* Vs = sm + 21760;          // pitch 68, 256 rows
    float* redmax = sm + 39168;      // [2][64]
    float* redsum = redmax + 128;    // [2][64]

    const int tid  = threadIdx.x;
    const int wid  = tid >> 5;
    const int lane = tid & 31;
    const int mw   = wid >> 1;        // 0..3 (16 q-rows)
    const int nw   = wid & 1;         // 0..1 (128 keys / 32 head-cols)
    const int r    = lane >> 2;
    const int c    = lane & 3;
    const int b    = blockIdx.y;

    const float* Qg = g_Q + (size_t)b * SEQ * HEAD;
    const float* Kg = g_K + (size_t)b * SEQ * HEAD;
    const float* Vg = g_V + (size_t)b * SEQ * HEAD;

    const int rowbase = mw*16 + r;

    #pragma unroll 1
    for (int half = 0; half < 2; half++) {
        const int qb = half ? (31 - (int)blockIdx.x) : (int)blockIdx.x;
        const int q0 = qb * 64;
        const int ntiles = q0 / 256 + 1;

        // stage Q (pre-scaled + tf32 at producer): 1024 f4, 4/thread
        #pragma unroll
        for (int it = 0; it < 4; it++) {
            int f = tid + it * 256, cc = f & 15, rr = f >> 4;
            CP_ASYNC16(s32(&Qs[rr*68 + 4*cc]),
                       &Qg[(size_t)(q0 + rr) * HEAD + 4*cc]);
        }
        CP_COMMIT();

        float m_st[2] = { -1e30f, -1e30f };
        float l_st[2] = { 0.f, 0.f };
        float o[4][4];
        #pragma unroll
        for (int nf = 0; nf < 4; nf++)
            #pragma unroll
            for (int e = 0; e < 4; e++) o[nf][e] = 0.f;

        for (int kt = 0; kt < ntiles; kt++) {
            const int k0 = kt * 256;
            __syncthreads();   // PV(kt-1) done with Ps(=Ks)/Vs; Q region free

            // stage K,V tiles 256x64 (4096 f4 each, 16+16 per thread)
            #pragma unroll
            for (int it = 0; it < 16; it++) {
                int f = tid + it * 256, cc = f & 15, rr = f >> 4;
                CP_ASYNC16(s32(&Ks[rr*68 + 4*cc]),
                           &Kg[(size_t)(k0 + rr) * HEAD + 4*cc]);
                CP_ASYNC16(s32(&Vs[rr*68 + 4*cc]),
                           &Vg[(size_t)(k0 + rr) * HEAD + 4*cc]);
            }
            CP_COMMIT();
            CP_WAIT0();
            __syncthreads();   // K,V (and Q on first tile) visible

            // ----- S = Q K^T : warp tile 16q x 128keys -----
            float s[16][4];
            #pragma unroll
            for (int nf = 0; nf < 16; nf++)
                #pragma unroll
                for (int e = 0; e < 4; e++) s[nf][e] = 0.f;

            #pragma unroll
            for (int ks = 0; ks < 8; ks++) {
                const int k = ks * 8;
                uint32_t a[4];
                a[0] = __float_as_uint(Qs[(mw*16 + r    )*68 + k + c    ]);
                a[1] = __float_as_uint(Qs[(mw*16 + r + 8)*68 + k + c    ]);
                a[2] = __float_as_uint(Qs[(mw*16 + r    )*68 + k + c + 4]);
                a[3] = __float_as_uint(Qs[(mw*16 + r + 8)*68 + k + c + 4]);
                #pragma unroll
                for (int nf = 0; nf < 16; nf++) {
                    const int n = nw*128 + nf*8;
                    uint32_t bb[2];
                    bb[0] = __float_as_uint(Ks[(n + r)*68 + k + c    ]);
                    bb[1] = __float_as_uint(Ks[(n + r)*68 + k + c + 4]);
                    mma_tf32(s[nf], a, bb);
                }
            }

            // ----- causal mask -----
            const int row0 = q0 + mw*16 + r;
            const int row1 = row0 + 8;
            if (k0 + 255 > q0) {
                #pragma unroll
                for (int nf = 0; nf < 16; nf++) {
                    const int col = k0 + nw*128 + nf*8 + 2*c;
                    if (col     > row0) s[nf][0] = -1e30f;
                    if (col + 1 > row0) s[nf][1] = -1e30f;
                    if (col     > row1) s[nf][2] = -1e30f;
                    if (col + 1 > row1) s[nf][3] = -1e30f;
                }
            }

            // ----- row max: intra-warp over c, 2-way cross-warp via smem ---
            float pm0 = s[0][0], pm1 = s[0][2];
            #pragma unroll
            for (int nf = 0; nf < 16; nf++) {
                pm0 = fmaxf(pm0, fmaxf(s[nf][0], s[nf][1]));
                pm1 = fmaxf(pm1, fmaxf(s[nf][2], s[nf][3]));
            }
            #pragma unroll
            for (int off = 1; off <= 2; off <<= 1) {
                pm0 = fmaxf(pm0, __shfl_xor_sync(0xffffffffu, pm0, off));
                pm1 = fmaxf(pm1, __shfl_xor_sync(0xffffffffu, pm1, off));
            }
            if (c == 0) {
                redmax[nw*64 + rowbase    ] = pm0;
                redmax[nw*64 + rowbase + 8] = pm1;
            }
            __syncthreads();   // (A) also: QK reads of Ks complete

            float mn0 = fmaxf(m_st[0], fmaxf(redmax[rowbase    ], redmax[64 + rowbase    ]));
            float mn1 = fmaxf(m_st[1], fmaxf(redmax[rowbase + 8], redmax[64 + rowbase + 8]));
            float corr0 = exp2f(m_st[0] - mn0);
            float corr1 = exp2f(m_st[1] - mn1);
            m_st[0] = mn0; m_st[1] = mn1;

            float rs0 = 0.f, rs1 = 0.f;
            #pragma unroll
            for (int nf = 0; nf < 16; nf++) {
                float p0 = exp2f(s[nf][0] - mn0);
                float p1 = exp2f(s[nf][1] - mn0);
                float p2 = exp2f(s[nf][2] - mn1);
                float p3 = exp2f(s[nf][3] - mn1);
                rs0 += p0 + p1;
                rs1 += p2 + p3;
                const int col = nw*128 + nf*8 + 2*c;
                *(float2*)&Ps[(rowbase    )*260 + col] =
                    make_float2(tf32r(p0), tf32r(p1));
                *(float2*)&Ps[(rowbase + 8)*260 + col] =
                    make_float2(tf32r(p2), tf32r(p3));
            }
            #pragma unroll
            for (int off = 1; off <= 2; off <<= 1) {
                rs0 += __shfl_xor_sync(0xffffffffu, rs0, off);
                rs1 += __shfl_xor_sync(0xffffffffu, rs1, off);
            }
            if (c == 0) {
                redsum[nw*64 + rowbase    ] = rs0;
                redsum[nw*64 + rowbase + 8] = rs1;
            }
            __syncthreads();   // (B) P + redsum visible

            l_st[0] = l_st[0] * corr0 + redsum[rowbase    ] + redsum[64 + rowbase    ];
            l_st[1] = l_st[1] * corr1 + redsum[rowbase + 8] + redsum[64 + rowbase + 8];

            #pragma unroll
            for (int nf = 0; nf < 4; nf++) {
                o[nf][0] *= corr0; o[nf][1] *= corr0;
                o[nf][2] *= corr1; o[nf][3] *= corr1;
            }

            // ----- O += P V : warp tile 16q x 32head, 32 k-steps -----
            #pragma unroll
            for (int ks = 0; ks < 32; ks++) {
                const int k = ks * 8;
                uint32_t a[4];
                a[0] = __float_as_uint(Ps[(mw*16 + r    )*260 + k + c    ]);
                a[1] = __float_as_uint(Ps[(mw*16 + r + 8)*260 + k + c    ]);
                a[2] = __float_as_uint(Ps[(mw*16 + r    )*260 + k + c + 4]);
                a[3] = __float_as_uint(Ps[(mw*16 + r + 8)*260 + k + c + 4]);
                #pragma unroll
                for (int nf = 0; nf < 4; nf++) {
                    const int n = nw*32 + nf*8;
                    uint32_t bb[2];
                    bb[0] = __float_as_uint(Vs[(k + c    )*68 + n + r]);
                    bb[1] = __float_as_uint(Vs[(k + c + 4)*68 + n + r]);
                    mma_tf32(o[nf], a, bb);
                }
            }
        }

        // epilogue: normalize, store
        const int row0 = q0 + mw*16 + r;
        const float inv0 = 1.f / l_st[0];
        const float inv1 = 1.f / l_st[1];
        #pragma unroll
        for (int nf = 0; nf < 4; nf++) {
            const int n = nw*32 + nf*8 + 2*c;
            *(float2*)&out[((size_t)b * SEQ + row0) * HEAD + n] =
                make_float2(o[nf][0] * inv0, o[nf][1] * inv0);
            *(float2*)&out[((size_t)b * SEQ + row0 + 8) * HEAD + n] =
                make_float2(o[nf][2] * inv1, o[nf][3] * inv1);
        }
        __syncthreads();   // all smem reads done before next half restages
    }
}

// ---------------------------------------------------------------------------
extern "C" void kernel_launch(void* const* d_in, const int* in_sizes, int n_in,
                              void* d_out, int out_size)
{
    const float* X  = (const float*)d_in[0];
    const float* Wq = (const float*)d_in[1];
    const float* Wk = (const float*)d_in[2];
    const float* Wv = (const float*)d_in[3];
    float* out = (float*)d_out;

    cudaFuncSetAttribute(qkv_mma,
                         cudaFuncAttributeMaxDynamicSharedMemorySize, QKV_SMEM_BYTES);
    cudaFuncSetAttribute(attn_mma,
                         cudaFuncAttributeMaxDynamicSharedMemorySize, ATTN_SMEM_BYTES);

    qkv_mma<<<128, 256, QKV_SMEM_BYTES>>>(X, Wq, Wk, Wv);

    dim3 g2(16, BATCH);
    attn_mma<<<g2, 256, ATTN_SMEM_BYTES>>>(out);
}